// round 2
// baseline (speedup 1.0000x reference)
#include <cuda_runtime.h>

#define NH   4096
#define NN   16384
#define DD   1024
#define EHH  8192
#define EOO  40960
#define EE   65536

// Scratch (no allocations allowed -> __device__ globals)
__device__ float g_A[(size_t)3 * NN * DD];   // A_t = n_f @ W_t[:D]
__device__ float g_B[(size_t)3 * NN * DD];   // B_t = n_f @ W_t[D:]
__device__ float g_z[(size_t)NN * DD];       // z_f accumulator
__device__ float g_ex[EE];                   // exp(logit)
__device__ float g_den[NN];                  // softmax denominators

// ---------------------------------------------------------------------------
__global__ void k_zero() {
    size_t i = (size_t)blockIdx.x * blockDim.x + threadIdx.x;
    g_z[i] = 0.f;
    if (i < NN) g_den[i] = 0.f;
}

// ---------------------------------------------------------------------------
// C[M=NN, N=DD] = A[M, DD] @ B[DD, DD]; all leading dims = DD. 128x128x8 tile.
#define BM 128
#define BN 128
#define BK 8

__global__ __launch_bounds__(256, 2)
void k_sgemm(const float* __restrict__ A, const float* __restrict__ B,
             float* __restrict__ C)
{
    __shared__ float As[BK][BM];
    __shared__ float Bs[BK][BN];
    const int tid = threadIdx.x;
    const int tx = tid & 15, ty = tid >> 4;
    const int arow = tid >> 1, acol = (tid & 1) * 4;
    const int brow = tid >> 5, bcol = (tid & 31) * 4;
    const int rowBase = blockIdx.y * BM;
    const int colBase = blockIdx.x * BN;

    const float* Aptr = A + (size_t)(rowBase + arow) * DD + acol;
    const float* Bptr = B + (size_t)brow * DD + colBase + bcol;

    float acc[8][8] = {};
    for (int k0 = 0; k0 < DD; k0 += BK) {
        float4 av = *(const float4*)(Aptr + k0);
        As[acol + 0][arow] = av.x;
        As[acol + 1][arow] = av.y;
        As[acol + 2][arow] = av.z;
        As[acol + 3][arow] = av.w;
        *(float4*)&Bs[brow][bcol] = *(const float4*)(Bptr + (size_t)k0 * DD);
        __syncthreads();
#pragma unroll
        for (int k = 0; k < BK; k++) {
            float ra[8], rb[8];
#pragma unroll
            for (int i = 0; i < 8; i++) ra[i] = As[k][ty * 8 + i];
#pragma unroll
            for (int j = 0; j < 8; j++) rb[j] = Bs[k][tx * 8 + j];
#pragma unroll
            for (int i = 0; i < 8; i++)
#pragma unroll
                for (int j = 0; j < 8; j++) acc[i][j] += ra[i] * rb[j];
        }
        __syncthreads();
    }
#pragma unroll
    for (int i = 0; i < 8; i++) {
        float* Cp = C + (size_t)(rowBase + ty * 8 + i) * DD + colBase + tx * 8;
        float4 v0 = {acc[i][0], acc[i][1], acc[i][2], acc[i][3]};
        float4 v1 = {acc[i][4], acc[i][5], acc[i][6], acc[i][7]};
        *(float4*)(Cp + 0) = v0;
        *(float4*)(Cp + 4) = v1;
    }
}

// ---------------------------------------------------------------------------
// Node apply: out = relu([n_f, z_f] @ Wn + bn), Wn per node type (rows <NH: hn)
__global__ __launch_bounds__(256, 2)
void k_nodeapply(const float* __restrict__ nf,
                 const float* __restrict__ Whn, const float* __restrict__ bhn,
                 const float* __restrict__ Won, const float* __restrict__ bon,
                 float* __restrict__ out)
{
    __shared__ float As[BK][BM];
    __shared__ float Bs[BK][BN];
    const int tid = threadIdx.x;
    const int tx = tid & 15, ty = tid >> 4;
    const int arow = tid >> 1, acol = (tid & 1) * 4;
    const int brow = tid >> 5, bcol = (tid & 31) * 4;
    const int rowBase = blockIdx.y * BM;
    const int colBase = blockIdx.x * BN;

    const float* W    = (rowBase < NH) ? Whn : Won;
    const float* bias = (rowBase < NH) ? bhn : bon;

    float acc[8][8] = {};
    for (int k0 = 0; k0 < 2 * DD; k0 += BK) {
        const float* Asrc = (k0 < DD)
            ? nf  + (size_t)(rowBase + arow) * DD + (k0 + acol)
            : g_z + (size_t)(rowBase + arow) * DD + (k0 - DD + acol);
        float4 av = *(const float4*)Asrc;
        As[acol + 0][arow] = av.x;
        As[acol + 1][arow] = av.y;
        As[acol + 2][arow] = av.z;
        As[acol + 3][arow] = av.w;
        *(float4*)&Bs[brow][bcol] =
            *(const float4*)(W + (size_t)(k0 + brow) * DD + colBase + bcol);
        __syncthreads();
#pragma unroll
        for (int k = 0; k < BK; k++) {
            float ra[8], rb[8];
#pragma unroll
            for (int i = 0; i < 8; i++) ra[i] = As[k][ty * 8 + i];
#pragma unroll
            for (int j = 0; j < 8; j++) rb[j] = Bs[k][tx * 8 + j];
#pragma unroll
            for (int i = 0; i < 8; i++)
#pragma unroll
                for (int j = 0; j < 8; j++) acc[i][j] += ra[i] * rb[j];
        }
        __syncthreads();
    }
#pragma unroll
    for (int i = 0; i < 8; i++) {
        const int row = rowBase + ty * 8 + i;
        float* Cp = out + (size_t)row * DD + colBase + tx * 8;
#pragma unroll
        for (int j = 0; j < 8; j += 4) {
            float4 v;
            v.x = fmaxf(acc[i][j + 0] + bias[colBase + tx * 8 + j + 0], 0.f);
            v.y = fmaxf(acc[i][j + 1] + bias[colBase + tx * 8 + j + 1], 0.f);
            v.z = fmaxf(acc[i][j + 2] + bias[colBase + tx * 8 + j + 2], 0.f);
            v.w = fmaxf(acc[i][j + 3] + bias[colBase + tx * 8 + j + 3], 0.f);
            *(float4*)(Cp + j) = v;
        }
    }
}

// ---------------------------------------------------------------------------
// Per-edge attention logit -> exp + denominator accumulation. One block/edge.
__global__ __launch_bounds__(256)
void k_edge_logit(const int* __restrict__ src, const int* __restrict__ dst,
                  const float* __restrict__ b_hh, const float* __restrict__ b_oo,
                  const float* __restrict__ b_ho,
                  const float* __restrict__ W_a, const float* __restrict__ b_a)
{
    const int e = blockIdx.x;
    const int t = (e < EHH) ? 0 : (e < EHH + EOO ? 1 : 2);
    const float* bias = (t == 0) ? b_hh : (t == 1 ? b_oo : b_ho);
    const int s = src[e], d = dst[e];
    const float4* Ar = (const float4*)(g_A + ((size_t)t * NN + s) * DD);
    const float4* Br = (const float4*)(g_B + ((size_t)t * NN + d) * DD);
    const float4* Bi = (const float4*)bias;
    const float4* Wa = (const float4*)W_a;

    const int i = threadIdx.x;           // 256 threads x float4 = 1024 elems
    float4 a = Ar[i], b = Br[i], c = Bi[i], w = Wa[i];
    float acc = fmaxf(a.x + b.x + c.x, 0.f) * w.x
              + fmaxf(a.y + b.y + c.y, 0.f) * w.y
              + fmaxf(a.z + b.z + c.z, 0.f) * w.z
              + fmaxf(a.w + b.w + c.w, 0.f) * w.w;

#pragma unroll
    for (int o = 16; o; o >>= 1) acc += __shfl_down_sync(0xffffffffu, acc, o);
    __shared__ float red[8];
    if ((threadIdx.x & 31) == 0) red[threadIdx.x >> 5] = acc;
    __syncthreads();
    if (threadIdx.x == 0) {
        float s2 = 0.f;
#pragma unroll
        for (int w8 = 0; w8 < 8; w8++) s2 += red[w8];
        float ex = expf(s2 + b_a[0]);
        g_ex[e] = ex;
        atomicAdd(&g_den[d], ex);
    }
}

// ---------------------------------------------------------------------------
// z_f[dst] += alpha_e * n_f[src]. One block/edge, scalar atomics.
__global__ __launch_bounds__(256)
void k_scatter(const int* __restrict__ src, const int* __restrict__ dst,
               const float* __restrict__ nf)
{
    const int e = blockIdx.x;
    const int s = src[e], d = dst[e];
    const float alpha = g_ex[e] / g_den[d];
    const float* nr = nf + (size_t)s * DD;
    float* zr = g_z + (size_t)d * DD;
#pragma unroll
    for (int i = threadIdx.x; i < DD; i += 256)
        atomicAdd(&zr[i], alpha * nr[i]);
}

// ---------------------------------------------------------------------------
extern "C" void kernel_launch(void* const* d_in, const int* in_sizes, int n_in,
                              void* d_out, int out_size)
{
    const float* n_f  = (const float*)d_in[0];
    const float* W_hh = (const float*)d_in[1];
    const float* b_hh = (const float*)d_in[2];
    const float* W_oo = (const float*)d_in[3];
    const float* b_oo = (const float*)d_in[4];
    const float* W_ho = (const float*)d_in[5];
    const float* b_ho = (const float*)d_in[6];
    const float* W_a  = (const float*)d_in[7];
    const float* b_a  = (const float*)d_in[8];
    const float* W_hn = (const float*)d_in[9];
    const float* b_hn = (const float*)d_in[10];
    const float* W_on = (const float*)d_in[11];
    const float* b_on = (const float*)d_in[12];
    const int*   esrc = (const int*)d_in[13];
    const int*   edst = (const int*)d_in[14];
    float* out = (float*)d_out;

    float *gA = nullptr, *gB = nullptr;
    cudaGetSymbolAddress((void**)&gA, g_A);
    cudaGetSymbolAddress((void**)&gB, g_B);

    k_zero<<<(NN * DD) / 256, 256>>>();

    dim3 gg(DD / BN, NN / BM);   // (8, 128)
    const float* Ws[3] = {W_hh, W_oo, W_ho};
    for (int t = 0; t < 3; t++) {
        k_sgemm<<<gg, 256>>>(n_f, Ws[t],                      gA + (size_t)t * NN * DD);
        k_sgemm<<<gg, 256>>>(n_f, Ws[t] + (size_t)DD * DD,    gB + (size_t)t * NN * DD);
    }

    k_edge_logit<<<EE, 256>>>(esrc, edst, b_hh, b_oo, b_ho, W_a, b_a);
    k_scatter<<<EE, 256>>>(esrc, edst, n_f);
    k_nodeapply<<<gg, 256>>>(n_f, W_hn, b_hn, W_on, b_on, out);
}

// round 7
// speedup vs baseline: 3.7093x; 3.7093x over previous
#include <cuda_runtime.h>
#include <cstdint>

#define NH   4096
#define NN   16384
#define DD   1024
#define EHH  8192
#define EOO  40960
#define EE   65536

// ---------------- GEMM tile config ----------------
#define BM      128
#define BN      128
#define BK      32
#define STAGES  3
#define LDP     (BK + 4)                     // padded row stride (floats)
#define A_STAGE_BYTES (BM * LDP * 4)         // 18432
#define STAGE_BYTES   (2 * BM * LDP * 4)     // 36864 (A + B)
#define DYN_SMEM (STAGES * STAGE_BYTES)      // 110592

// ---------------- scratch (__device__ globals; no allocs allowed) ----------
__device__ float g_A[(size_t)3 * NN * DD];      // A_t = n_f @ W_t[:D]
__device__ float g_B[(size_t)3 * NN * DD];      // B_t = n_f @ W_t[D:]
__device__ float g_z[(size_t)NN * DD];          // z_f accumulator (fp32 -> tf32)
__device__ float g_nf[(size_t)NN * DD];         // tf32-rounded copy of n_f
__device__ float g_ex[EE];                      // exp(logit)
__device__ float g_den[NN];                     // softmax denominators
__device__ float g_Wp[(size_t)6 * DD * DD];     // 6 proj weights, transposed [N,K], tf32
__device__ float g_Wn[(size_t)2 * DD * 2 * DD]; // 2 node weights, transposed [N,2K], tf32

// ---------------- helpers ---------------------------------------------------
__device__ __forceinline__ float to_tf32(float x) {
    uint32_t o;
    asm("cvt.rna.tf32.f32 %0, %1;" : "=r"(o) : "f"(x));
    return __uint_as_float(o);
}
__device__ __forceinline__ uint32_t smem_u32(const void* p) {
    uint32_t a;
    asm("{ .reg .u64 t; cvta.to.shared.u64 t, %1; cvt.u32.u64 %0, t; }"
        : "=r"(a) : "l"(p));
    return a;
}
__device__ __forceinline__ void cp_async16(uint32_t dst, const void* src) {
    asm volatile("cp.async.cg.shared.global [%0], [%1], 16;"
                 :: "r"(dst), "l"(src) : "memory");
}
#define CP_COMMIT()  asm volatile("cp.async.commit_group;" ::: "memory")
#define CP_WAIT1()   asm volatile("cp.async.wait_group 1;" ::: "memory")

__device__ __forceinline__ void mma8(float* c, const float* a, const float* b) {
    asm volatile(
        "mma.sync.aligned.m16n8k8.row.col.f32.tf32.tf32.f32 "
        "{%0,%1,%2,%3}, {%4,%5,%6,%7}, {%8,%9}, {%0,%1,%2,%3};"
        : "+f"(c[0]), "+f"(c[1]), "+f"(c[2]), "+f"(c[3])
        : "r"(__float_as_uint(a[0])), "r"(__float_as_uint(a[1])),
          "r"(__float_as_uint(a[2])), "r"(__float_as_uint(a[3])),
          "r"(__float_as_uint(b[0])), "r"(__float_as_uint(b[1])));
}

// ---------------------------------------------------------------------------
__global__ void k_zero() {
    size_t i = (size_t)blockIdx.x * blockDim.x + threadIdx.x;
    g_z[i] = 0.f;
    if (i < NN) g_den[i] = 0.f;
}

// round n_f -> g_nf (tf32 quantization done once, not per-fragment)
__global__ void k_cvt_nf(const float* __restrict__ src) {
    size_t i = (size_t)blockIdx.x * blockDim.x + threadIdx.x;
    float4 v = ((const float4*)src)[i];
    v.x = to_tf32(v.x); v.y = to_tf32(v.y); v.z = to_tf32(v.z); v.w = to_tf32(v.w);
    ((float4*)g_nf)[i] = v;
}
// round g_z in place after scatter
__global__ void k_round_z() {
    size_t i = (size_t)blockIdx.x * blockDim.x + threadIdx.x;
    float4 v = ((float4*)g_z)[i];
    v.x = to_tf32(v.x); v.y = to_tf32(v.y); v.z = to_tf32(v.z); v.w = to_tf32(v.w);
    ((float4*)g_z)[i] = v;
}

// transpose + tf32 round: dst[n*K + k] = tf32(src[k*Nn + n])
__global__ void k_transpose(const float* __restrict__ src, float* __restrict__ dst,
                            int K, int Nn) {
    __shared__ float t[32][33];
    const int k0 = blockIdx.x * 32, n0 = blockIdx.y * 32;
    const int x = threadIdx.x, y = threadIdx.y;
#pragma unroll
    for (int i = y; i < 32; i += 8)
        t[i][x] = src[(size_t)(k0 + i) * Nn + n0 + x];
    __syncthreads();
#pragma unroll
    for (int i = y; i < 32; i += 8)
        dst[(size_t)(n0 + i) * K + k0 + x] = to_tf32(t[x][i]);
}

// ---------------------------------------------------------------------------
// tf32 mma.sync GEMM: C[BMxBN tile] = A[rowBase:, :K] @ W^T[colBase:, :K]
// A0 for k<DD, A1 for k>=DD (both ld=DD). W is [N,K] row-major, ld=ldB.
__device__ __forceinline__ void gemm_body(
    char* smem, int tid,
    const float* A0, const float* A1, const float* W, int ldB, int K,
    int rowBase, int colBase, float* outp, const float* bias, bool relu)
{
    const int lane = tid & 31, wid = tid >> 5;
    const int grp = lane >> 2, t4 = lane & 3;
    const int wm = wid >> 1, wn = wid & 1;

    const uint32_t sb = smem_u32(smem);
    const int vr = tid >> 3;            // vector row base (0..31)
    const int kv = (tid & 7) * 4;       // k offset of 16B vector

    const int KT = K / BK;

    // prefetch one stage
    auto prefetch = [&](int st, int kt) {
        const int k0 = kt * BK;
        const float* Asrc = (k0 < DD) ? A0 : A1;
        const int kk = (k0 < DD) ? k0 : k0 - DD;
        const uint32_t sA = sb + st * STAGE_BYTES;
        const uint32_t sB = sA + A_STAGE_BYTES;
#pragma unroll
        for (int i = 0; i < 4; i++) {
            const int r = vr + i * 32;
            cp_async16(sA + (uint32_t)(r * LDP + kv) * 4,
                       Asrc + (size_t)(rowBase + r) * DD + kk + kv);
            cp_async16(sB + (uint32_t)(r * LDP + kv) * 4,
                       W + (size_t)(colBase + r) * ldB + k0 + kv);
        }
        CP_COMMIT();
    };

    prefetch(0, 0);
    prefetch(1, 1);

    float acc[2][8][4] = {};

    for (int kt = 0; kt < KT; kt++) {
        CP_WAIT1();
        __syncthreads();
        if (kt + 2 < KT) prefetch((kt + 2) % STAGES, kt + 2);
        else CP_COMMIT();                       // keep group count consistent

        const int st = kt % STAGES;
        const float* As = (const float*)(smem + st * STAGE_BYTES);
        const float* Bs = (const float*)(smem + st * STAGE_BYTES + A_STAGE_BYTES);

#pragma unroll
        for (int ks = 0; ks < 4; ks++) {
            const int kb = ks * 8;
            float a[2][4], b[8][2];
#pragma unroll
            for (int mi = 0; mi < 2; mi++) {
                const int r0 = wm * 32 + mi * 16 + grp;
                a[mi][0] = As[(r0    ) * LDP + kb + t4    ];
                a[mi][1] = As[(r0 + 8) * LDP + kb + t4    ];
                a[mi][2] = As[(r0    ) * LDP + kb + t4 + 4];
                a[mi][3] = As[(r0 + 8) * LDP + kb + t4 + 4];
            }
#pragma unroll
            for (int ni = 0; ni < 8; ni++) {
                const int c0 = wn * 64 + ni * 8 + grp;
                b[ni][0] = Bs[c0 * LDP + kb + t4    ];
                b[ni][1] = Bs[c0 * LDP + kb + t4 + 4];
            }
#pragma unroll
            for (int mi = 0; mi < 2; mi++)
#pragma unroll
                for (int ni = 0; ni < 8; ni++)
                    mma8(acc[mi][ni], a[mi], b[ni]);
        }
    }

    // epilogue
#pragma unroll
    for (int mi = 0; mi < 2; mi++) {
#pragma unroll
        for (int ni = 0; ni < 8; ni++) {
            const int row = rowBase + wm * 32 + mi * 16 + grp;
            const int col = colBase + wn * 64 + ni * 8 + t4 * 2;
            float2 v0 = {acc[mi][ni][0], acc[mi][ni][1]};
            float2 v1 = {acc[mi][ni][2], acc[mi][ni][3]};
            if (relu) {
                const float b0 = bias[col], b1 = bias[col + 1];
                v0.x = fmaxf(v0.x + b0, 0.f); v0.y = fmaxf(v0.y + b1, 0.f);
                v1.x = fmaxf(v1.x + b0, 0.f); v1.y = fmaxf(v1.y + b1, 0.f);
            }
            *(float2*)(outp + (size_t)row * DD + col) = v0;
            *(float2*)(outp + (size_t)(row + 8) * DD + col) = v1;
        }
    }
}

// Projection GEMMs: z in [0,6) selects weight slab; out = g_A/g_B slab.
__global__ __launch_bounds__(256, 2)
void k_gemm_proj(const float* __restrict__ Wp, float* gA, float* gB)
{
    extern __shared__ char smem[];
    const int z = blockIdx.z;
    float* outp = ((z & 1) ? gB : gA) + (size_t)(z >> 1) * NN * DD;
    gemm_body(smem, threadIdx.x, g_nf, g_nf, Wp + (size_t)z * DD * DD, DD, DD,
              blockIdx.y * BM, blockIdx.x * BN, outp, nullptr, false);
}

// Node apply: A = [g_nf | g_z] (K=2048), W per node type, bias+relu epilogue.
__global__ __launch_bounds__(256, 2)
void k_gemm_node(const float* __restrict__ Wn,
                 const float* __restrict__ bhn, const float* __restrict__ bon,
                 float* out)
{
    extern __shared__ char smem[];
    const int rowBase = blockIdx.y * BM;
    const float* W    = (rowBase < NH) ? Wn  : Wn + (size_t)2 * DD * DD;
    const float* bias = (rowBase < NH) ? bhn : bon;
    gemm_body(smem, threadIdx.x, g_nf, g_z, W, 2 * DD, 2 * DD,
              rowBase, blockIdx.x * BN, out, bias, true);
}

// ---------------------------------------------------------------------------
__global__ __launch_bounds__(256)
void k_edge_logit(const int* __restrict__ src, const int* __restrict__ dst,
                  const float* __restrict__ b_hh, const float* __restrict__ b_oo,
                  const float* __restrict__ b_ho,
                  const float* __restrict__ W_a, const float* __restrict__ b_a)
{
    const int e = blockIdx.x;
    const int t = (e < EHH) ? 0 : (e < EHH + EOO ? 1 : 2);
    const float* bias = (t == 0) ? b_hh : (t == 1 ? b_oo : b_ho);
    const int s = src[e], d = dst[e];
    const float4* Ar = (const float4*)(g_A + ((size_t)t * NN + s) * DD);
    const float4* Br = (const float4*)(g_B + ((size_t)t * NN + d) * DD);
    const float4* Bi = (const float4*)bias;
    const float4* Wa = (const float4*)W_a;

    const int i = threadIdx.x;
    float4 a = Ar[i], b = Br[i], c = Bi[i], w = Wa[i];
    float acc = fmaxf(a.x + b.x + c.x, 0.f) * w.x
              + fmaxf(a.y + b.y + c.y, 0.f) * w.y
              + fmaxf(a.z + b.z + c.z, 0.f) * w.z
              + fmaxf(a.w + b.w + c.w, 0.f) * w.w;
#pragma unroll
    for (int o = 16; o; o >>= 1) acc += __shfl_down_sync(0xffffffffu, acc, o);
    __shared__ float red[8];
    if ((threadIdx.x & 31) == 0) red[threadIdx.x >> 5] = acc;
    __syncthreads();
    if (threadIdx.x == 0) {
        float s2 = 0.f;
#pragma unroll
        for (int w8 = 0; w8 < 8; w8++) s2 += red[w8];
        float ex = expf(s2 + b_a[0]);
        g_ex[e] = ex;
        atomicAdd(&g_den[d], ex);
    }
}

__global__ __launch_bounds__(256)
void k_scatter(const int* __restrict__ src, const int* __restrict__ dst,
               const float* __restrict__ nf)
{
    const int e = blockIdx.x;
    const int s = src[e], d = dst[e];
    const float alpha = g_ex[e] / g_den[d];
    const float* nr = nf + (size_t)s * DD;
    float* zr = g_z + (size_t)d * DD;
#pragma unroll
    for (int i = threadIdx.x; i < DD; i += 256)
        atomicAdd(&zr[i], alpha * nr[i]);
}

// ---------------------------------------------------------------------------
extern "C" void kernel_launch(void* const* d_in, const int* in_sizes, int n_in,
                              void* d_out, int out_size)
{
    const float* n_f  = (const float*)d_in[0];
    const float* W_hh = (const float*)d_in[1];
    const float* b_hh = (const float*)d_in[2];
    const float* W_oo = (const float*)d_in[3];
    const float* b_oo = (const float*)d_in[4];
    const float* W_ho = (const float*)d_in[5];
    const float* b_ho = (const float*)d_in[6];
    const float* W_a  = (const float*)d_in[7];
    const float* b_a  = (const float*)d_in[8];
    const float* W_hn = (const float*)d_in[9];
    const float* b_hn = (const float*)d_in[10];
    const float* W_on = (const float*)d_in[11];
    const float* b_on = (const float*)d_in[12];
    const int*   esrc = (const int*)d_in[13];
    const int*   edst = (const int*)d_in[14];
    float* out = (float*)d_out;

    float *gA, *gB, *gWp, *gWn;
    cudaGetSymbolAddress((void**)&gA, g_A);
    cudaGetSymbolAddress((void**)&gB, g_B);
    cudaGetSymbolAddress((void**)&gWp, g_Wp);
    cudaGetSymbolAddress((void**)&gWn, g_Wn);

    cudaFuncSetAttribute(k_gemm_proj, cudaFuncAttributeMaxDynamicSharedMemorySize, DYN_SMEM);
    cudaFuncSetAttribute(k_gemm_node, cudaFuncAttributeMaxDynamicSharedMemorySize, DYN_SMEM);

    k_zero<<<(NN * DD) / 256, 256>>>();
    k_cvt_nf<<<(NN * DD / 4) / 256, 256>>>(n_f);

    // Weight transposes (+ tf32 rounding) into [N, K] scratch
    const float* Ws[3] = {W_hh, W_oo, W_ho};
    dim3 tb(32, 8);
    for (int t = 0; t < 3; t++)
        for (int h = 0; h < 2; h++)
            k_transpose<<<dim3(32, 32), tb>>>(Ws[t] + (size_t)h * DD * DD,
                                              gWp + (size_t)(t * 2 + h) * DD * DD, DD, DD);
    k_transpose<<<dim3(64, 32), tb>>>(W_hn, gWn, 2 * DD, DD);
    k_transpose<<<dim3(64, 32), tb>>>(W_on, gWn + (size_t)2 * DD * DD, 2 * DD, DD);

    // 6 projection GEMMs in one launch (z-dim selects weight)
    k_gemm_proj<<<dim3(DD / BN, NN / BM, 6), 256, DYN_SMEM>>>(gWp, gA, gB);

    k_edge_logit<<<EE, 256>>>(esrc, edst, b_hh, b_oo, b_ho, W_a, b_a);
    k_scatter<<<EE, 256>>>(esrc, edst, n_f);
    k_round_z<<<(NN * DD / 4) / 256, 256>>>();

    k_gemm_node<<<dim3(DD / BN, NN / BM), 256, DYN_SMEM>>>(gWn, b_hn, b_on, out);
}